// round 14
// baseline (speedup 1.0000x reference)
#include <cuda_runtime.h>
#include <cuda_bf16.h>

#define TSTEPS  400
#define POS_INF __int_as_float(0x7f800000)
#define HI0     28.5f          // safe upper bound on E_255 (true bound 28.1)
#define HI1     15.4f          // safe upper bound on E_127 (true bound 15.3)

// Exact reference simulation for rare rows. Matches the JAX reference op-for-op.
__device__ __noinline__ float sm2_slow_row(const float* __restrict__ row) {
    float I = 1.0f, n = 0.0f, EF = 2.5f;
    for (int t = 0; t < TSTEPS; ++t) {
        float p = row[t];
        float q = p * 5.0f;
        bool correct = (q >= 3.0f);
        bool brk = (p == -1.0f);
        float In;
        if (n >= 2.0f)      In = I * EF;
        else if (n == 1.0f) In = 6.0f;
        else                In = 1.0f;
        if (!correct) In = 1.0f;
        if (!brk) I = In;
        I = fminf(fmaxf(I, 1.0f), 274.0f);
        float d = 5.0f - q;
        EF = EF + (0.1f - d * (0.08f + d * 0.02f));
        EF = fmaxf(EF, 1.3f);
        if (correct) n += 1.0f;
    }
    return I;
}

// delta(p) = 0.1 - d*(0.08 + 0.02 d),  d = 5 - 5p
__device__ __forceinline__ float delta_of(float pv) {
    float d  = fmaf(pv, -5.0f, 5.0f);
    float t2 = fmaf(d, 0.02f, 0.08f);
    return fmaf(-d, t2, 0.1f);
}

// MEDIUM path (~0.7% of rows): extend window to [128,384). Outlined so its
// registers don't inflate the fast path (R10 lesson).
__device__ __noinline__ void medium_path(const float* __restrict__ rp, int q,
                                         float Sg, float Mg, int cg,
                                         float* E383, int* okg) {
    unsigned am = __activemask();
    const float* mp = rp + 128 + q * 32;       // lane q: steps [128+32q, 160+32q)
    float s2 = 0.0f, mn2 = POS_INF;
    int   c2 = 0;
    #pragma unroll 2
    for (int j = 0; j < 8; ++j) {
        float4 v = __ldcs(reinterpret_cast<const float4*>(mp + j * 4));
        float pv[4] = {v.x, v.y, v.z, v.w};
        #pragma unroll
        for (int k = 0; k < 4; ++k) {
            s2 += delta_of(pv[k]);
            mn2 = fminf(mn2, s2);
            c2 += (pv[k] >= 0.6f);
        }
    }
    float m2 = 1.3f + (s2 - mn2);
    #pragma unroll
    for (int off = 1; off <= 2; off <<= 1) {
        float so = __shfl_down_sync(am, s2, off, 4);
        float mo = __shfl_down_sync(am, m2, off, 4);
        int   co = __shfl_down_sync(am, c2, off, 4);
        m2 = fmaxf(m2 + so, mo);
        s2 = s2 + so;
        c2 = c2 + co;
    }
    // compose [128,256) then [256,384): s' = s2+Sg, m' = max(m2+Sg, Mg)
    float sX = __shfl_sync(am, s2, 0, 4) + Sg;
    float mX = fmaxf(__shfl_sync(am, m2, 0, 4) + Sg, Mg);
    int   cX = __shfl_sync(am, c2, 0, 4) + cg;
    *okg = (mX >= HI1 + sX) && (cX >= 2);      // collapse from E_127 bound (~13 sigma)
    *E383 = mX;
}

__global__ void __launch_bounds__(256, 6)
sm2_kernel(const float* __restrict__ p, float* __restrict__ out, int B) {
    const unsigned FULL = 0xFFFFFFFFu;
    int gwarp = (blockIdx.x * blockDim.x + threadIdx.x) >> 5;
    int lane  = threadIdx.x & 31;
    int q     = lane & 3;                      // position within 4-lane row group

    int row0 = gwarp * 8 + (lane >> 2);        // 8 rows per warp
    int row  = (row0 < B) ? row0 : (B - 1);    // clamp: full warp active for shfl
    const float* rp = p + (size_t)row * TSTEPS;

    // ---- window loads (streaming: read-once data, evict-first) ----
    // Window [256,384) = 16 segments of 8 steps; lane q owns segments
    // {q, 4+q, 8+q, 12+q}; group lanes 32B apart -> ~1 line/row per instr.
    float4 wv[4][2];
    #pragma unroll
    for (int cch = 0; cch < 4; ++cch) {
        const float* a = rp + 256 + cch * 32 + q * 8;
        wv[cch][0] = __ldcs(reinterpret_cast<const float4*>(a));
        wv[cch][1] = __ldcs(reinterpret_cast<const float4*>(a + 4));
    }

    // ---- fold each owned 8-step segment: prefix-sum + running-min + count ----
    float sc[4], mc[4];
    int c = 0;
    #pragma unroll
    for (int cch = 0; cch < 4; ++cch) {
        float s = 0.0f, mn = POS_INF;
        #pragma unroll
        for (int h = 0; h < 2; ++h) {
            float pv[4] = {wv[cch][h].x, wv[cch][h].y, wv[cch][h].z, wv[cch][h].w};
            #pragma unroll
            for (int k = 0; k < 4; ++k) {
                s += delta_of(pv[k]);
                mn = fminf(mn, s);
                if ((k & 1) == 0)
                    c += (pv[k] >= 0.6f);  // conservative undercount; guard only
            }
        }
        sc[cch] = s;
        mc[cch] = 1.3f + (s - mn);
    }

    // tail loads issued after the fold (shorter live range; latency overlaps
    // the tree reduce + collapse check below)
    float4 tb[4];
    #pragma unroll
    for (int j = 0; j < 4; ++j)
        tb[j] = __ldcs(reinterpret_cast<const float4*>(rp + 384 + j * 4));

    // ---- tree reduce each chunk across the 4 lanes (ordered), + count ----
    #pragma unroll
    for (int off = 1; off <= 2; off <<= 1) {
        #pragma unroll
        for (int cch = 0; cch < 4; ++cch) {
            float so = __shfl_down_sync(FULL, sc[cch], off, 4);
            float mo = __shfl_down_sync(FULL, mc[cch], off, 4);
            mc[cch] = fmaxf(mc[cch] + so, mo);   // self earlier in time, other later
            sc[cch] = sc[cch] + so;
        }
        c += __shfl_down_sync(FULL, c, off, 4);
    }
    // Leader: compose the 4 chunks in time order.
    float s = sc[0], m = mc[0];
    #pragma unroll
    for (int cch = 1; cch < 4; ++cch) {
        m = fmaxf(m + sc[cch], mc[cch]);
        s = s + sc[cch];
    }

    float Mg = __shfl_sync(FULL, m, 0, 4);     // window composition (group-wide)
    float Sg = __shfl_sync(FULL, s, 0, 4);
    int   cg = __shfl_sync(FULL, c, 0, 4);
    int okg = (Mg >= HI0 + Sg) && (cg >= 2);   // collapse from E_255 bound + guard

    float E383 = Mg;
    if (!okg)
        medium_path(rp, q, Sg, Mg, cg, &E383, &okg);

    // ---- tail t = 384..399: direct I simulation ----
    float E = E383;              // E_{t-1} entering step t
    float I = 1.0f;              // exact: any pre-384 run erased by first incorrect
    int allc = 1;
    #pragma unroll
    for (int j = 0; j < 4; ++j) {
        float pv[4] = {tb[j].x, tb[j].y, tb[j].z, tb[j].w};
        #pragma unroll
        for (int k = 0; k < 4; ++k) {
            bool corr = (pv[k] * 5.0f >= 3.0f);      // exact reference predicate
            I = corr ? fminf(I * E, 274.0f) : 1.0f;  // uses EF_{t-1}; progressive clip
            allc &= (int)corr;
            E = fmaxf(E + delta_of(pv[k]), 1.3f);
        }
    }

    if (!okg || allc)
        I = sm2_slow_row(rp);    // ~0.2 rows expected; exact resimulation

    if (q == 0 && row0 < B)
        out[row] = fminf(2.0f * I, 274.0f);
}

extern "C" void kernel_launch(void* const* d_in, const int* in_sizes, int n_in,
                              void* d_out, int out_size) {
    const float* p = (const float*)d_in[0];
    float* out = (float*)d_out;
    int B = out_size;
    int rowsPerBlock = 64;               // 256 threads = 8 warps * 8 rows
    int blocks = (B + rowsPerBlock - 1) / rowsPerBlock;
    sm2_kernel<<<blocks, 256>>>(p, out, B);
}

// round 15
// speedup vs baseline: 1.0267x; 1.0267x over previous
#include <cuda_runtime.h>
#include <cuda_bf16.h>

#define TSTEPS  400
#define POS_INF __int_as_float(0x7f800000)
#define HI0     28.5f          // safe upper bound on E_255 (true bound 28.1)
#define HI1     15.4f          // safe upper bound on E_127 (true bound 15.3)

// Exact reference simulation for rare rows. Matches the JAX reference op-for-op.
__device__ __noinline__ float sm2_slow_row(const float* __restrict__ row) {
    float I = 1.0f, n = 0.0f, EF = 2.5f;
    for (int t = 0; t < TSTEPS; ++t) {
        float p = row[t];
        float q = p * 5.0f;
        bool correct = (q >= 3.0f);
        bool brk = (p == -1.0f);
        float In;
        if (n >= 2.0f)      In = I * EF;
        else if (n == 1.0f) In = 6.0f;
        else                In = 1.0f;
        if (!correct) In = 1.0f;
        if (!brk) I = In;
        I = fminf(fmaxf(I, 1.0f), 274.0f);
        float d = 5.0f - q;
        EF = EF + (0.1f - d * (0.08f + d * 0.02f));
        EF = fmaxf(EF, 1.3f);
        if (correct) n += 1.0f;
    }
    return I;
}

// delta(p) = 0.1 - d*(0.08 + 0.02 d),  d = 5 - 5p
__device__ __forceinline__ float delta_of(float pv) {
    float d  = fmaf(pv, -5.0f, 5.0f);
    float t2 = fmaf(d, 0.02f, 0.08f);
    return fmaf(-d, t2, 0.1f);
}

// MEDIUM path (~0.7% of rows): extend window to [128,384). Outlined so its
// registers don't inflate the fast path (R10 lesson).
__device__ __noinline__ void medium_path(const float* __restrict__ rp, int q,
                                         float Sg, float Mg, int cg,
                                         float* E383, int* okg) {
    unsigned am = __activemask();
    const float* mp = rp + 128 + q * 32;       // lane q: steps [128+32q, 160+32q)
    float s2 = 0.0f, mn2 = POS_INF;
    int   c2 = 0;
    #pragma unroll 2
    for (int j = 0; j < 8; ++j) {
        float4 v = *reinterpret_cast<const float4*>(mp + j * 4);
        float pv[4] = {v.x, v.y, v.z, v.w};
        #pragma unroll
        for (int k = 0; k < 4; ++k) {
            s2 += delta_of(pv[k]);
            mn2 = fminf(mn2, s2);
            c2 += (pv[k] >= 0.6f);
        }
    }
    float m2 = 1.3f + (s2 - mn2);
    #pragma unroll
    for (int off = 1; off <= 2; off <<= 1) {
        float so = __shfl_down_sync(am, s2, off, 4);
        float mo = __shfl_down_sync(am, m2, off, 4);
        int   co = __shfl_down_sync(am, c2, off, 4);
        m2 = fmaxf(m2 + so, mo);
        s2 = s2 + so;
        c2 = c2 + co;
    }
    // compose [128,256) then [256,384): s' = s2+Sg, m' = max(m2+Sg, Mg)
    float sX = __shfl_sync(am, s2, 0, 4) + Sg;
    float mX = fmaxf(__shfl_sync(am, m2, 0, 4) + Sg, Mg);
    int   cX = __shfl_sync(am, c2, 0, 4) + cg;
    *okg = (mX >= HI1 + sX) && (cX >= 2);      // collapse from E_127 bound (~13 sigma)
    *E383 = mX;
}

__global__ void __launch_bounds__(256, 6)
sm2_kernel(const float* __restrict__ p, float* __restrict__ out, int B) {
    const unsigned FULL = 0xFFFFFFFFu;
    int gwarp = (blockIdx.x * blockDim.x + threadIdx.x) >> 5;
    int lane  = threadIdx.x & 31;
    int q     = lane & 3;                      // position within 4-lane row group

    int row0 = gwarp * 8 + (lane >> 2);        // 8 rows per warp
    int row  = (row0 < B) ? row0 : (B - 1);    // clamp: full warp active for shfl
    const float* rp = p + (size_t)row * TSTEPS;

    // ---- fast-path loads (hoisted; 12 LDG.128 in flight per lane) ----
    // Window [256,384) = 16 segments of 8 steps; lane q owns segments
    // {q, 4+q, 8+q, 12+q}; group lanes 32B apart -> ~1 line/row per instr.
    float4 wv[4][2];
    #pragma unroll
    for (int cch = 0; cch < 4; ++cch) {
        const float* a = rp + 256 + cch * 32 + q * 8;
        wv[cch][0] = *reinterpret_cast<const float4*>(a);
        wv[cch][1] = *reinterpret_cast<const float4*>(a + 4);
    }
    // tail: steps [384,400), broadcast to all 4 lanes of the group
    float4 tb[4];
    #pragma unroll
    for (int j = 0; j < 4; ++j)
        tb[j] = *reinterpret_cast<const float4*>(rp + 384 + j * 4);

    // ---- fold each owned 8-step segment: prefix-sum + running-min + count ----
    float sc[4], mc[4];
    int c = 0;
    #pragma unroll
    for (int cch = 0; cch < 4; ++cch) {
        float s = 0.0f, mn = POS_INF;
        #pragma unroll
        for (int h = 0; h < 2; ++h) {
            float pv[4] = {wv[cch][h].x, wv[cch][h].y, wv[cch][h].z, wv[cch][h].w};
            #pragma unroll
            for (int k = 0; k < 4; ++k) {
                s += delta_of(pv[k]);
                mn = fminf(mn, s);
                if ((k & 1) == 0)
                    c += (pv[k] >= 0.6f);  // conservative undercount; guard only
            }
        }
        sc[cch] = s;
        mc[cch] = 1.3f + (s - mn);
    }

    // ---- tree reduce each chunk across the 4 lanes (ordered), + count ----
    #pragma unroll
    for (int off = 1; off <= 2; off <<= 1) {
        #pragma unroll
        for (int cch = 0; cch < 4; ++cch) {
            float so = __shfl_down_sync(FULL, sc[cch], off, 4);
            float mo = __shfl_down_sync(FULL, mc[cch], off, 4);
            mc[cch] = fmaxf(mc[cch] + so, mo);   // self earlier in time, other later
            sc[cch] = sc[cch] + so;
        }
        c += __shfl_down_sync(FULL, c, off, 4);
    }
    // Leader: compose the 4 chunks in time order.
    float s = sc[0], m = mc[0];
    #pragma unroll
    for (int cch = 1; cch < 4; ++cch) {
        m = fmaxf(m + sc[cch], mc[cch]);
        s = s + sc[cch];
    }

    float Mg = __shfl_sync(FULL, m, 0, 4);     // window composition (group-wide)
    float Sg = __shfl_sync(FULL, s, 0, 4);
    int   cg = __shfl_sync(FULL, c, 0, 4);
    int okg = (Mg >= HI0 + Sg) && (cg >= 2);   // collapse from E_255 bound + guard

    float E383 = Mg;
    if (!okg)
        medium_path(rp, q, Sg, Mg, cg, &E383, &okg);

    // ---- tail t = 384..399: direct I simulation ----
    float E = E383;              // E_{t-1} entering step t
    float I = 1.0f;              // exact: any pre-384 run erased by first incorrect
    int allc = 1;
    #pragma unroll
    for (int j = 0; j < 4; ++j) {
        float pv[4] = {tb[j].x, tb[j].y, tb[j].z, tb[j].w};
        #pragma unroll
        for (int k = 0; k < 4; ++k) {
            bool corr = (pv[k] * 5.0f >= 3.0f);      // exact reference predicate
            I = corr ? fminf(I * E, 274.0f) : 1.0f;  // uses EF_{t-1}; progressive clip
            allc &= (int)corr;
            E = fmaxf(E + delta_of(pv[k]), 1.3f);
        }
    }

    if (!okg || allc)
        I = sm2_slow_row(rp);    // ~0.2 rows expected; exact resimulation

    if (q == 0 && row0 < B)
        out[row] = fminf(2.0f * I, 274.0f);
}

extern "C" void kernel_launch(void* const* d_in, const int* in_sizes, int n_in,
                              void* d_out, int out_size) {
    const float* p = (const float*)d_in[0];
    float* out = (float*)d_out;
    int B = out_size;
    int rowsPerBlock = 64;               // 256 threads = 8 warps * 8 rows
    int blocks = (B + rowsPerBlock - 1) / rowsPerBlock;
    sm2_kernel<<<blocks, 256>>>(p, out, B);
}